// round 15
// baseline (speedup 1.0000x reference)
#include <cuda_runtime.h>
#include <cuda_fp16.h>
#include <cstdint>
#include <math.h>

#define N_NODES 100000
#define N_EDGES 3200000
#define F_IN    512
#define HID     128
#define N_CLS   16

typedef unsigned short u16;

// ---------------- scratch (static device globals; no allocation) ----------
__device__ int   g_cnt[N_NODES];
__device__ int   g_off[N_NODES];
__device__ float g_dinv[N_NODES];
__device__ int   g_total;
__device__ int   g_rank[N_EDGES];                 // per-edge slot within row
__device__ int   g_ccol[N_EDGES];
__device__ u16   g_bufA[(size_t)N_NODES * HID];   // GEMM1 out (h1 pre-agg, fp16)
__device__ u16   g_bufG[(size_t)N_NODES * N_CLS]; // g = relu(Â h1) Q  (fp16)
__device__ u16   g_w1h[HID * F_IN];               // fp16 W1, [n][k]
__device__ float g_Q[HID * N_CLS];                // Q = W2 @ W3^T (fp32)

// ---------------- helpers ---------------------------------------------------
__device__ __forceinline__ uint32_t smem_to_u32(const void* p) {
    uint32_t a;
    asm("{ .reg .u64 t; cvta.to.shared.u64 t, %1; cvt.u32.u64 %0, t; }"
        : "=r"(a) : "l"(p));
    return a;
}

#define LDSM4(r0, r1, r2, r3, addr)                                        \
    asm volatile("ldmatrix.sync.aligned.m8n8.x4.shared.b16 {%0,%1,%2,%3}, [%4];" \
                 : "=r"(r0), "=r"(r1), "=r"(r2), "=r"(r3) : "r"(addr))

#define MMA_F16(d, a, b)                                                   \
    asm volatile("mma.sync.aligned.m16n8k16.row.col.f32.f16.f16.f32 "      \
                 "{%0,%1,%2,%3}, {%4,%5,%6,%7}, {%8,%9}, {%0,%1,%2,%3};"   \
                 : "+f"((d)[0]), "+f"((d)[1]), "+f"((d)[2]), "+f"((d)[3])  \
                 : "r"((a)[0]), "r"((a)[1]), "r"((a)[2]), "r"((a)[3]),     \
                   "r"((b)[0]), "r"((b)[1]))

// ---------------- CSR construction ----------------------------------------
__global__ void count_kernel(const int* __restrict__ rows, int E) {
    int e = blockIdx.x * blockDim.x + threadIdx.x;
    if (e < E) g_rank[e] = atomicAdd(&g_cnt[rows[e]], 1);
}

// offsets + dinv fused
__global__ void offsets_kernel(int n, float fill) {
    __shared__ int s[1024];
    __shared__ int base;
    int t = threadIdx.x;
    int i = blockIdx.x * 1024 + t;
    int v = (i < n) ? g_cnt[i] : 0;
    if (i < n) g_dinv[i] = rsqrtf((float)v + fill);
    s[t] = v;
    __syncthreads();
    for (int d = 1; d < 1024; d <<= 1) {
        int u = (t >= d) ? s[t - d] : 0;
        __syncthreads();
        s[t] += u;
        __syncthreads();
    }
    if (t == 1023) base = atomicAdd(&g_total, s[1023]);
    __syncthreads();
    if (i < n) g_off[i] = base + s[t] - v;
}

// atomic-free fill: pure stream read + scatter
__global__ void fill_kernel(const int* __restrict__ rows,
                            const int* __restrict__ cols, int E) {
    int e = blockIdx.x * blockDim.x + threadIdx.x;
    if (e < E)
        g_ccol[g_off[rows[e]] + g_rank[e]] = cols[e];
}

// ---------------- W1 prep (main stream, bandwidth-bound) -------------------
__global__ void w1prep_kernel(const float* __restrict__ W1) {
    int i = blockIdx.x * blockDim.x + threadIdx.x;
    if (i < HID * F_IN) {
        int n = i / F_IN, k = i % F_IN;
        __half h = __float2half_rn(W1[k * HID + n]);
        g_w1h[i] = *reinterpret_cast<u16*>(&h);
    }
}

// ---------------- Q prep (side stream; hidden under GEMM1) -----------------
__global__ void qprep_kernel(const float* __restrict__ W2,
                             const float* __restrict__ W3) {
    int i = blockIdx.x * blockDim.x + threadIdx.x;   // i = k*N_CLS + c
    if (i < HID * N_CLS) {
        int k = i / N_CLS, c = i % N_CLS;
        float s = 0.f;
#pragma unroll 8
        for (int q = 0; q < HID; q++)
            s += W2[k * HID + q] * W3[c * HID + q];
        g_Q[k * N_CLS + c] = s;
    }
}

// ---------------- HMMA fp16 GEMM (unchanged from R8 WIN) -------------------
#define BM   128
#define KCC  32
#define PADK 40
#define SMB  10240

__device__ __forceinline__ uint32_t qaddr(uint32_t base, int row0, int kb) {
    int L = threadIdx.x & 31;
    int r = row0 + (L & 15);
    int k = kb + (L >> 4) * 8;
    return base + (uint32_t)(r * (PADK * 2) + k * 2);
}

__global__ void __launch_bounds__(256, 2)
mmagemm_kernel(const float* __restrict__ Af,
               const u16* __restrict__ B,
               u16* __restrict__ C, int M, int K) {
    extern __shared__ __align__(16) char sm[];

    int tid  = threadIdx.x;
    int wid  = tid >> 5;
    int lane = tid & 31;
    int wr   = wid & 3;
    int wc   = wid >> 2;
    int m0   = blockIdx.x * BM;

    uint32_t sb = smem_to_u32(sm);
    float acc[2][8][4];
#pragma unroll
    for (int mt = 0; mt < 2; mt++)
#pragma unroll
        for (int nt = 0; nt < 8; nt++)
#pragma unroll
            for (int e = 0; e < 4; e++) acc[mt][nt][e] = 0.f;

    int arf = tid >> 3, aqf = tid & 7;
    int r16 = tid >> 2, q16 = tid & 3;

    float4 pa[4];
    uint4  pbv[2];

#pragma unroll
    for (int i = 0; i < 4; i++) {
        int r = arf + i * 32;
        pa[i] = make_float4(0.f, 0.f, 0.f, 0.f);
        if (m0 + r < M)
            pa[i] = *(const float4*)&Af[(size_t)(m0 + r) * K + aqf * 4];
    }
#pragma unroll
    for (int i = 0; i < 2; i++)
        pbv[i] = *(const uint4*)&B[(size_t)(r16 + i * 64) * K + q16 * 8];
    {
        u16* BsP = (u16*)(sm);
        u16* AsP = (u16*)(sm + 2 * SMB);
#pragma unroll
        for (int i = 0; i < 2; i++)
            *(uint4*)&BsP[(r16 + i * 64) * PADK + q16 * 8] = pbv[i];
#pragma unroll
        for (int i = 0; i < 4; i++) {
            __half2 h0 = __floats2half2_rn(pa[i].x, pa[i].y);
            __half2 h1 = __floats2half2_rn(pa[i].z, pa[i].w);
            *(uint2*)&AsP[(arf + i * 32) * PADK + aqf * 4] =
                make_uint2(*(unsigned*)&h0, *(unsigned*)&h1);
        }
    }
    __syncthreads();

    int nc = K / KCC;
    for (int c = 0; c < nc; c++) {
        int s = c & 1;
        if (c + 1 < nc) {
            int k0 = (c + 1) * KCC;
#pragma unroll
            for (int i = 0; i < 4; i++) {
                int r = arf + i * 32;
                pa[i] = make_float4(0.f, 0.f, 0.f, 0.f);
                if (m0 + r < M)
                    pa[i] = *(const float4*)&Af[(size_t)(m0 + r) * K + k0 + aqf * 4];
            }
#pragma unroll
            for (int i = 0; i < 2; i++)
                pbv[i] = *(const uint4*)&B[(size_t)(r16 + i * 64) * K + k0 + q16 * 8];
        }

        uint32_t bs_base = sb + s * SMB;
        uint32_t as_base = sb + 2 * SMB + s * SMB;
#pragma unroll
        for (int ks = 0; ks < KCC; ks += 16) {
            uint32_t bf[8][2];
#pragma unroll
            for (int g = 0; g < 4; g++) {
                uint32_t r0, r1, r2, r3;
                LDSM4(r0, r1, r2, r3, qaddr(bs_base, wc * 64 + g * 16, ks));
                bf[g * 2][0] = r0; bf[g * 2][1] = r2;
                bf[g * 2 + 1][0] = r1; bf[g * 2 + 1][1] = r3;
            }
            uint32_t ah[2][4];
#pragma unroll
            for (int mt = 0; mt < 2; mt++)
                LDSM4(ah[mt][0], ah[mt][1], ah[mt][2], ah[mt][3],
                      qaddr(as_base, wr * 32 + mt * 16, ks));
#pragma unroll
            for (int mt = 0; mt < 2; mt++)
#pragma unroll
                for (int nt = 0; nt < 8; nt++)
                    MMA_F16(acc[mt][nt], ah[mt], bf[nt]);
        }

        if (c + 1 < nc) {
            int s2 = 1 - s;
            u16* BsP = (u16*)(sm + s2 * SMB);
            u16* AsP = (u16*)(sm + 2 * SMB + s2 * SMB);
#pragma unroll
            for (int i = 0; i < 2; i++)
                *(uint4*)&BsP[(r16 + i * 64) * PADK + q16 * 8] = pbv[i];
#pragma unroll
            for (int i = 0; i < 4; i++) {
                __half2 h0 = __floats2half2_rn(pa[i].x, pa[i].y);
                __half2 h1 = __floats2half2_rn(pa[i].z, pa[i].w);
                *(uint2*)&AsP[(arf + i * 32) * PADK + aqf * 4] =
                    make_uint2(*(unsigned*)&h0, *(unsigned*)&h1);
            }
        }
        __syncthreads();
    }

    int rbase = m0 + wr * 32 + (lane >> 2);
    int cbase = wc * 64 + (lane & 3) * 2;
#pragma unroll
    for (int mt = 0; mt < 2; mt++)
#pragma unroll
        for (int nt = 0; nt < 8; nt++) {
            int r = rbase + mt * 16;
            int cc = cbase + nt * 8;
            if (r < M) {
                __half2 v = __floats2half2_rn(acc[mt][nt][0], acc[mt][nt][1]);
                *(unsigned*)&C[(size_t)r * 128 + cc] = *reinterpret_cast<unsigned*>(&v);
            }
            if (r + 8 < M) {
                __half2 v = __floats2half2_rn(acc[mt][nt][2], acc[mt][nt][3]);
                *(unsigned*)&C[(size_t)(r + 8) * 128 + cc] = *reinterpret_cast<unsigned*>(&v);
            }
        }
}

// ---------------- agg1 + Q epilogue ----------------------------------------
__device__ __forceinline__ void gacc(float4& acc, float w, uint2 raw) {
    float2 f0 = __half22float2(*reinterpret_cast<__half2*>(&raw.x));
    float2 f1 = __half22float2(*reinterpret_cast<__half2*>(&raw.y));
    acc.x += w * f0.x; acc.y += w * f0.y;
    acc.z += w * f1.x; acc.w += w * f1.y;
}

__global__ void agg1q_kernel(const u16* __restrict__ h,
                             u16* __restrict__ g, int n, float fill) {
    __shared__ float sQ[N_CLS * HID];   // sQ[c*128 + k]
    for (int i = threadIdx.x; i < N_CLS * HID; i += blockDim.x) {
        int c = i / HID, k = i % HID;
        sQ[i] = g_Q[k * N_CLS + c];
    }
    __syncthreads();

    int warp = (blockIdx.x * blockDim.x + threadIdx.x) >> 5;
    int lane = threadIdx.x & 31;
    if (warp >= n) return;
    const uint2* hv = (const uint2*)h;

    float di = g_dinv[warp];
    float ws = fill * di * di;
    float4 acc = make_float4(0.f, 0.f, 0.f, 0.f);
    gacc(acc, ws, hv[(size_t)warp * 32 + lane]);

    int s = g_off[warp];
    int c = g_cnt[warp];
    int j = 0;
    for (; j + 8 <= c; j += 8) {
        int cols[8];
#pragma unroll
        for (int q = 0; q < 8; q++) cols[q] = __ldg(&g_ccol[s + j + q]);
        uint2 u[8];
#pragma unroll
        for (int q = 0; q < 8; q++) u[q] = hv[(size_t)cols[q] * 32 + lane];
        float w[8];
#pragma unroll
        for (int q = 0; q < 8; q++) w[q] = di * __ldg(&g_dinv[cols[q]]);
#pragma unroll
        for (int q = 0; q < 8; q++) gacc(acc, w[q], u[q]);
    }
    for (; j < c; j++) {
        int col = __ldg(&g_ccol[s + j]);
        float w = di * __ldg(&g_dinv[col]);
        gacc(acc, w, hv[(size_t)col * 32 + lane]);
    }
    acc.x = fmaxf(acc.x, 0.f);
    acc.y = fmaxf(acc.y, 0.f);
    acc.z = fmaxf(acc.z, 0.f);
    acc.w = fmaxf(acc.w, 0.f);

    // epilogue: g[row][cc] = sum_k a[k] * Q[k][cc]  (fp16 store)
#pragma unroll
    for (int cc = 0; cc < N_CLS; cc++) {
        float4 q = *(const float4*)&sQ[cc * 128 + lane * 4];
        float  p = acc.x * q.x + acc.y * q.y + acc.z * q.z + acc.w * q.w;
        p += __shfl_xor_sync(0xffffffffu, p, 16);
        p += __shfl_xor_sync(0xffffffffu, p, 8);
        p += __shfl_xor_sync(0xffffffffu, p, 4);
        p += __shfl_xor_sync(0xffffffffu, p, 2);
        p += __shfl_xor_sync(0xffffffffu, p, 1);
        if (lane == 0) {
            __half hv16 = __float2half_rn(p);
            g[(size_t)warp * N_CLS + cc] = *reinterpret_cast<u16*>(&hv16);
        }
    }
}

// ---------------- agg2: out = Â g + b3  (16 fp16 features) -----------------
__global__ void agg2_kernel(const u16* __restrict__ g,
                            const float* __restrict__ b3,
                            float* __restrict__ out, int n, float fill) {
    __shared__ float sb[N_CLS];
    if (threadIdx.x < N_CLS) sb[threadIdx.x] = b3[threadIdx.x];
    __syncthreads();

    int wp   = (blockIdx.x * blockDim.x + threadIdx.x) >> 5;
    int lane = threadIdx.x & 31;
    int half = lane >> 4, lp = lane & 15;
    int row  = wp * 2 + half;
    if (wp * 2 >= n) return;
    bool active = row < n;
    int rsafe = active ? row : 0;

    float di = active ? g_dinv[rsafe] : 0.f;
    float ws = fill * di * di;
    float acc = ws * __half2float(
        *reinterpret_cast<const __half*>(&g[(size_t)rsafe * N_CLS + lp]));

    int s = g_off[rsafe];
    int c = active ? g_cnt[rsafe] : 0;
    int cO = __shfl_xor_sync(0xffffffffu, c, 16);
    int cm = max(c, cO);
    for (int j = 0; j < cm; j += 8) {
        int cols[8];
        float w[8];
#pragma unroll
        for (int q = 0; q < 8; q++) {
            bool act = (j + q) < c;
            cols[q] = act ? __ldg(&g_ccol[s + j + q]) : rsafe;
            w[q]    = act ? di * __ldg(&g_dinv[cols[q]]) : 0.f;
        }
#pragma unroll
        for (int q = 0; q < 8; q++) {
            float gv = __half2float(*reinterpret_cast<const __half*>(
                &g[(size_t)cols[q] * N_CLS + lp]));
            acc += w[q] * gv;
        }
    }
    if (active) out[(size_t)row * N_CLS + lp] = acc + sb[lp];
}

// ---------------- launch ---------------------------------------------------
extern "C" void kernel_launch(void* const* d_in, const int* in_sizes, int n_in,
                              void* d_out, int out_size) {
    const float* x  = (const float*)d_in[0];
    const int*   ei = (const int*)d_in[1];
    const float* W1 = (const float*)d_in[2];
    const float* W2 = (const float*)d_in[3];
    const float* W3 = (const float*)d_in[4];
    const float* b3 = (const float*)d_in[5];
    float* out = (float*)d_out;

    const int E = in_sizes[1] / 2;
    const int N = in_sizes[0] / F_IN;
    const int* rows = ei;
    const int* cols = ei + E;
    const float fill = truncf(log2f((float)E / (float)N));

    u16* bufA; cudaGetSymbolAddress((void**)&bufA, g_bufA);
    u16* bufG; cudaGetSymbolAddress((void**)&bufG, g_bufG);
    u16* w1h;  cudaGetSymbolAddress((void**)&w1h, g_w1h);
    int* cntp; cudaGetSymbolAddress((void**)&cntp, g_cnt);
    int* totp; cudaGetSymbolAddress((void**)&totp, g_total);

    cudaFuncSetAttribute(mmagemm_kernel,
                         cudaFuncAttributeMaxDynamicSharedMemorySize, 4 * SMB);

    const int T = 256;
    const int GB = (N + BM - 1) / BM;

    cudaStream_t s2;
    cudaStreamCreateWithFlags(&s2, cudaStreamNonBlocking);
    cudaEvent_t eFork, eJoin;
    cudaEventCreateWithFlags(&eFork, cudaEventDisableTiming);
    cudaEventCreateWithFlags(&eJoin, cudaEventDisableTiming);

    // fork: CSR build + qprep on side stream, overlaps w1prep + GEMM1
    cudaEventRecord(eFork, 0);
    cudaStreamWaitEvent(s2, eFork, 0);

    cudaMemsetAsync(cntp, 0, N_NODES * sizeof(int), s2);
    cudaMemsetAsync(totp, 0, sizeof(int), s2);
    count_kernel<<<(E + T - 1) / T, T, 0, s2>>>(rows, E);
    offsets_kernel<<<(N + 1023) / 1024, 1024, 0, s2>>>(N, fill);
    fill_kernel<<<(E + T - 1) / T, T, 0, s2>>>(rows, cols, E);
    qprep_kernel<<<(HID * N_CLS + T - 1) / T, T, 0, s2>>>(W2, W3);
    cudaEventRecord(eJoin, s2);

    w1prep_kernel<<<(HID * F_IN + T - 1) / T, T>>>(W1);
    mmagemm_kernel<<<GB, 256, 4 * SMB>>>(x, w1h, bufA, N, F_IN);

    // join, then agg1 (+Q epilogue) and the 16-wide second aggregation
    cudaStreamWaitEvent(0, eJoin, 0);
    agg1q_kernel<<<(N * 32 + T - 1) / T, T>>>(bufA, bufG, N, fill);
    {
        int warps = (N + 1) / 2;
        agg2_kernel<<<(warps * 32 + T - 1) / T, T>>>(bufG, b3, out, N, fill);
    }

    cudaEventDestroy(eFork);
    cudaEventDestroy(eJoin);
    cudaStreamDestroy(s2);
}

// round 16
// speedup vs baseline: 1.0224x; 1.0224x over previous
#include <cuda_runtime.h>
#include <cuda_fp16.h>
#include <cstdint>
#include <math.h>

#define N_NODES 100000
#define N_EDGES 3200000
#define F_IN    512
#define HID     128
#define N_CLS   16

typedef unsigned short u16;

// ---------------- scratch (static device globals; no allocation) ----------
__device__ int   g_cnt[N_NODES];
__device__ int   g_off[N_NODES];
__device__ float g_dinv[N_NODES];
__device__ int   g_total;
__device__ int   g_rank[N_EDGES];                 // per-edge slot within row
__device__ int   g_ccol[N_EDGES];
__device__ u16   g_bufA[(size_t)N_NODES * HID];   // GEMM1 out (h1 pre-agg, fp16)
__device__ u16   g_bufG[(size_t)N_NODES * N_CLS]; // g = relu(Â h1) Q  (fp16)
__device__ u16   g_w1h[HID * F_IN];               // fp16 W1, [n][k]
__device__ float g_Q[HID * N_CLS];                // Q = W2 @ W3^T (fp32)

// ---------------- helpers ---------------------------------------------------
__device__ __forceinline__ uint32_t smem_to_u32(const void* p) {
    uint32_t a;
    asm("{ .reg .u64 t; cvta.to.shared.u64 t, %1; cvt.u32.u64 %0, t; }"
        : "=r"(a) : "l"(p));
    return a;
}

#define LDSM4(r0, r1, r2, r3, addr)                                        \
    asm volatile("ldmatrix.sync.aligned.m8n8.x4.shared.b16 {%0,%1,%2,%3}, [%4];" \
                 : "=r"(r0), "=r"(r1), "=r"(r2), "=r"(r3) : "r"(addr))

#define MMA_F16(d, a, b)                                                   \
    asm volatile("mma.sync.aligned.m16n8k16.row.col.f32.f16.f16.f32 "      \
                 "{%0,%1,%2,%3}, {%4,%5,%6,%7}, {%8,%9}, {%0,%1,%2,%3};"   \
                 : "+f"((d)[0]), "+f"((d)[1]), "+f"((d)[2]), "+f"((d)[3])  \
                 : "r"((a)[0]), "r"((a)[1]), "r"((a)[2]), "r"((a)[3]),     \
                   "r"((b)[0]), "r"((b)[1]))

// ---------------- CSR construction ----------------------------------------
__global__ void count_kernel(const int* __restrict__ rows, int E) {
    int e = blockIdx.x * blockDim.x + threadIdx.x;
    if (e == 0) g_total = 0;   // offsets runs after count in-stream
    if (e < E) g_rank[e] = atomicAdd(&g_cnt[rows[e]], 1);
}

// offsets + dinv + Q (fused): first OFF_BLOCKS do the scan, trailing
// Q_BLOCKS compute Q = W2 @ W3^T with warp-per-output reduction.
#define OFF_BLOCKS ((N_NODES + 1023) / 1024)
#define Q_BLOCKS   ((HID * N_CLS * 32 + 1023) / 1024)   // 64

__global__ void offsets_q_kernel(int n, float fill,
                                 const float* __restrict__ W2,
                                 const float* __restrict__ W3) {
    if (blockIdx.x >= OFF_BLOCKS) {
        int wg   = (blockIdx.x - OFF_BLOCKS) * 32 + (threadIdx.x >> 5);
        int lane = threadIdx.x & 31;
        if (wg < HID * N_CLS) {
            int k = wg / N_CLS, c = wg % N_CLS;
            float s = 0.f;
#pragma unroll
            for (int q = 0; q < 4; q++)
                s += W2[k * HID + lane + q * 32] * W3[c * HID + lane + q * 32];
            s += __shfl_xor_sync(0xffffffffu, s, 16);
            s += __shfl_xor_sync(0xffffffffu, s, 8);
            s += __shfl_xor_sync(0xffffffffu, s, 4);
            s += __shfl_xor_sync(0xffffffffu, s, 2);
            s += __shfl_xor_sync(0xffffffffu, s, 1);
            if (lane == 0) g_Q[k * N_CLS + c] = s;
        }
        return;
    }
    __shared__ int s[1024];
    __shared__ int base;
    int t = threadIdx.x;
    int i = blockIdx.x * 1024 + t;
    int v = (i < n) ? g_cnt[i] : 0;
    if (i < n) g_dinv[i] = rsqrtf((float)v + fill);
    s[t] = v;
    __syncthreads();
    for (int d = 1; d < 1024; d <<= 1) {
        int u = (t >= d) ? s[t - d] : 0;
        __syncthreads();
        s[t] += u;
        __syncthreads();
    }
    if (t == 1023) base = atomicAdd(&g_total, s[1023]);
    __syncthreads();
    if (i < n) g_off[i] = base + s[t] - v;
}

// atomic-free fill: pure stream read + scatter
__global__ void fill_kernel(const int* __restrict__ rows,
                            const int* __restrict__ cols, int E) {
    int e = blockIdx.x * blockDim.x + threadIdx.x;
    if (e < E)
        g_ccol[g_off[rows[e]] + g_rank[e]] = cols[e];
}

// ---------------- W1 prep (main stream, bandwidth-bound) -------------------
__global__ void w1prep_kernel(const float* __restrict__ W1) {
    int i = blockIdx.x * blockDim.x + threadIdx.x;
    if (i < HID * F_IN) {
        int n = i / F_IN, k = i % F_IN;
        __half h = __float2half_rn(W1[k * HID + n]);
        g_w1h[i] = *reinterpret_cast<u16*>(&h);
    }
}

// ---------------- HMMA fp16 GEMM (unchanged from R8 WIN) -------------------
#define BM   128
#define KCC  32
#define PADK 40
#define SMB  10240

__device__ __forceinline__ uint32_t qaddr(uint32_t base, int row0, int kb) {
    int L = threadIdx.x & 31;
    int r = row0 + (L & 15);
    int k = kb + (L >> 4) * 8;
    return base + (uint32_t)(r * (PADK * 2) + k * 2);
}

__global__ void __launch_bounds__(256, 2)
mmagemm_kernel(const float* __restrict__ Af,
               const u16* __restrict__ B,
               u16* __restrict__ C, int M, int K) {
    extern __shared__ __align__(16) char sm[];

    int tid  = threadIdx.x;
    int wid  = tid >> 5;
    int lane = tid & 31;
    int wr   = wid & 3;
    int wc   = wid >> 2;
    int m0   = blockIdx.x * BM;

    uint32_t sb = smem_to_u32(sm);
    float acc[2][8][4];
#pragma unroll
    for (int mt = 0; mt < 2; mt++)
#pragma unroll
        for (int nt = 0; nt < 8; nt++)
#pragma unroll
            for (int e = 0; e < 4; e++) acc[mt][nt][e] = 0.f;

    int arf = tid >> 3, aqf = tid & 7;
    int r16 = tid >> 2, q16 = tid & 3;

    float4 pa[4];
    uint4  pbv[2];

#pragma unroll
    for (int i = 0; i < 4; i++) {
        int r = arf + i * 32;
        pa[i] = make_float4(0.f, 0.f, 0.f, 0.f);
        if (m0 + r < M)
            pa[i] = *(const float4*)&Af[(size_t)(m0 + r) * K + aqf * 4];
    }
#pragma unroll
    for (int i = 0; i < 2; i++)
        pbv[i] = *(const uint4*)&B[(size_t)(r16 + i * 64) * K + q16 * 8];
    {
        u16* BsP = (u16*)(sm);
        u16* AsP = (u16*)(sm + 2 * SMB);
#pragma unroll
        for (int i = 0; i < 2; i++)
            *(uint4*)&BsP[(r16 + i * 64) * PADK + q16 * 8] = pbv[i];
#pragma unroll
        for (int i = 0; i < 4; i++) {
            __half2 h0 = __floats2half2_rn(pa[i].x, pa[i].y);
            __half2 h1 = __floats2half2_rn(pa[i].z, pa[i].w);
            *(uint2*)&AsP[(arf + i * 32) * PADK + aqf * 4] =
                make_uint2(*(unsigned*)&h0, *(unsigned*)&h1);
        }
    }
    __syncthreads();

    int nc = K / KCC;
    for (int c = 0; c < nc; c++) {
        int s = c & 1;
        if (c + 1 < nc) {
            int k0 = (c + 1) * KCC;
#pragma unroll
            for (int i = 0; i < 4; i++) {
                int r = arf + i * 32;
                pa[i] = make_float4(0.f, 0.f, 0.f, 0.f);
                if (m0 + r < M)
                    pa[i] = *(const float4*)&Af[(size_t)(m0 + r) * K + k0 + aqf * 4];
            }
#pragma unroll
            for (int i = 0; i < 2; i++)
                pbv[i] = *(const uint4*)&B[(size_t)(r16 + i * 64) * K + k0 + q16 * 8];
        }

        uint32_t bs_base = sb + s * SMB;
        uint32_t as_base = sb + 2 * SMB + s * SMB;
#pragma unroll
        for (int ks = 0; ks < KCC; ks += 16) {
            uint32_t bf[8][2];
#pragma unroll
            for (int g = 0; g < 4; g++) {
                uint32_t r0, r1, r2, r3;
                LDSM4(r0, r1, r2, r3, qaddr(bs_base, wc * 64 + g * 16, ks));
                bf[g * 2][0] = r0; bf[g * 2][1] = r2;
                bf[g * 2 + 1][0] = r1; bf[g * 2 + 1][1] = r3;
            }
            uint32_t ah[2][4];
#pragma unroll
            for (int mt = 0; mt < 2; mt++)
                LDSM4(ah[mt][0], ah[mt][1], ah[mt][2], ah[mt][3],
                      qaddr(as_base, wr * 32 + mt * 16, ks));
#pragma unroll
            for (int mt = 0; mt < 2; mt++)
#pragma unroll
                for (int nt = 0; nt < 8; nt++)
                    MMA_F16(acc[mt][nt], ah[mt], bf[nt]);
        }

        if (c + 1 < nc) {
            int s2 = 1 - s;
            u16* BsP = (u16*)(sm + s2 * SMB);
            u16* AsP = (u16*)(sm + 2 * SMB + s2 * SMB);
#pragma unroll
            for (int i = 0; i < 2; i++)
                *(uint4*)&BsP[(r16 + i * 64) * PADK + q16 * 8] = pbv[i];
#pragma unroll
            for (int i = 0; i < 4; i++) {
                __half2 h0 = __floats2half2_rn(pa[i].x, pa[i].y);
                __half2 h1 = __floats2half2_rn(pa[i].z, pa[i].w);
                *(uint2*)&AsP[(arf + i * 32) * PADK + aqf * 4] =
                    make_uint2(*(unsigned*)&h0, *(unsigned*)&h1);
            }
        }
        __syncthreads();
    }

    int rbase = m0 + wr * 32 + (lane >> 2);
    int cbase = wc * 64 + (lane & 3) * 2;
#pragma unroll
    for (int mt = 0; mt < 2; mt++)
#pragma unroll
        for (int nt = 0; nt < 8; nt++) {
            int r = rbase + mt * 16;
            int cc = cbase + nt * 8;
            if (r < M) {
                __half2 v = __floats2half2_rn(acc[mt][nt][0], acc[mt][nt][1]);
                *(unsigned*)&C[(size_t)r * 128 + cc] = *reinterpret_cast<unsigned*>(&v);
            }
            if (r + 8 < M) {
                __half2 v = __floats2half2_rn(acc[mt][nt][2], acc[mt][nt][3]);
                *(unsigned*)&C[(size_t)(r + 8) * 128 + cc] = *reinterpret_cast<unsigned*>(&v);
            }
        }
}

// ---------------- agg1 + Q epilogue ----------------------------------------
__device__ __forceinline__ void gacc(float4& acc, float w, uint2 raw) {
    float2 f0 = __half22float2(*reinterpret_cast<__half2*>(&raw.x));
    float2 f1 = __half22float2(*reinterpret_cast<__half2*>(&raw.y));
    acc.x += w * f0.x; acc.y += w * f0.y;
    acc.z += w * f1.x; acc.w += w * f1.y;
}

__global__ void agg1q_kernel(const u16* __restrict__ h,
                             u16* __restrict__ g, int n, float fill) {
    __shared__ float sQ[N_CLS * HID];   // sQ[c*128 + k]
    for (int i = threadIdx.x; i < N_CLS * HID; i += blockDim.x) {
        int c = i / HID, k = i % HID;
        sQ[i] = g_Q[k * N_CLS + c];
    }
    __syncthreads();

    int warp = (blockIdx.x * blockDim.x + threadIdx.x) >> 5;
    int lane = threadIdx.x & 31;
    if (warp >= n) return;
    const uint2* hv = (const uint2*)h;

    float di = g_dinv[warp];
    float ws = fill * di * di;
    float4 acc = make_float4(0.f, 0.f, 0.f, 0.f);
    gacc(acc, ws, hv[(size_t)warp * 32 + lane]);

    int s = g_off[warp];
    int c = g_cnt[warp];
    int j = 0;
    for (; j + 8 <= c; j += 8) {
        int cols[8];
#pragma unroll
        for (int q = 0; q < 8; q++) cols[q] = __ldg(&g_ccol[s + j + q]);
        uint2 u[8];
#pragma unroll
        for (int q = 0; q < 8; q++) u[q] = hv[(size_t)cols[q] * 32 + lane];
        float w[8];
#pragma unroll
        for (int q = 0; q < 8; q++) w[q] = di * __ldg(&g_dinv[cols[q]]);
#pragma unroll
        for (int q = 0; q < 8; q++) gacc(acc, w[q], u[q]);
    }
    for (; j < c; j++) {
        int col = __ldg(&g_ccol[s + j]);
        float w = di * __ldg(&g_dinv[col]);
        gacc(acc, w, hv[(size_t)col * 32 + lane]);
    }
    acc.x = fmaxf(acc.x, 0.f);
    acc.y = fmaxf(acc.y, 0.f);
    acc.z = fmaxf(acc.z, 0.f);
    acc.w = fmaxf(acc.w, 0.f);

    // epilogue: g[row][cc] = sum_k a[k] * Q[k][cc]  (fp16 store)
#pragma unroll
    for (int cc = 0; cc < N_CLS; cc++) {
        float4 q = *(const float4*)&sQ[cc * 128 + lane * 4];
        float  p = acc.x * q.x + acc.y * q.y + acc.z * q.z + acc.w * q.w;
        p += __shfl_xor_sync(0xffffffffu, p, 16);
        p += __shfl_xor_sync(0xffffffffu, p, 8);
        p += __shfl_xor_sync(0xffffffffu, p, 4);
        p += __shfl_xor_sync(0xffffffffu, p, 2);
        p += __shfl_xor_sync(0xffffffffu, p, 1);
        if (lane == 0) {
            __half hv16 = __float2half_rn(p);
            g[(size_t)warp * N_CLS + cc] = *reinterpret_cast<u16*>(&hv16);
        }
    }
}

// ---------------- agg2: out = Â g + b3  (16 fp16 features) -----------------
__global__ void agg2_kernel(const u16* __restrict__ g,
                            const float* __restrict__ b3,
                            float* __restrict__ out, int n, float fill) {
    __shared__ float sb[N_CLS];
    if (threadIdx.x < N_CLS) sb[threadIdx.x] = b3[threadIdx.x];
    __syncthreads();

    int wp   = (blockIdx.x * blockDim.x + threadIdx.x) >> 5;
    int lane = threadIdx.x & 31;
    int half = lane >> 4, lp = lane & 15;
    int row  = wp * 2 + half;
    if (wp * 2 >= n) return;
    bool active = row < n;
    int rsafe = active ? row : 0;

    float di = active ? g_dinv[rsafe] : 0.f;
    float ws = fill * di * di;
    float acc = ws * __half2float(
        *reinterpret_cast<const __half*>(&g[(size_t)rsafe * N_CLS + lp]));

    int s = g_off[rsafe];
    int c = active ? g_cnt[rsafe] : 0;
    int cO = __shfl_xor_sync(0xffffffffu, c, 16);
    int cm = max(c, cO);
    for (int j = 0; j < cm; j += 8) {
        int cols[8];
        float w[8];
#pragma unroll
        for (int q = 0; q < 8; q++) {
            bool act = (j + q) < c;
            cols[q] = act ? __ldg(&g_ccol[s + j + q]) : rsafe;
            w[q]    = act ? di * __ldg(&g_dinv[cols[q]]) : 0.f;
        }
#pragma unroll
        for (int q = 0; q < 8; q++) {
            float gv = __half2float(*reinterpret_cast<const __half*>(
                &g[(size_t)cols[q] * N_CLS + lp]));
            acc += w[q] * gv;
        }
    }
    if (active) out[(size_t)row * N_CLS + lp] = acc + sb[lp];
}

// ---------------- launch ---------------------------------------------------
extern "C" void kernel_launch(void* const* d_in, const int* in_sizes, int n_in,
                              void* d_out, int out_size) {
    const float* x  = (const float*)d_in[0];
    const int*   ei = (const int*)d_in[1];
    const float* W1 = (const float*)d_in[2];
    const float* W2 = (const float*)d_in[3];
    const float* W3 = (const float*)d_in[4];
    const float* b3 = (const float*)d_in[5];
    float* out = (float*)d_out;

    const int E = in_sizes[1] / 2;
    const int N = in_sizes[0] / F_IN;
    const int* rows = ei;
    const int* cols = ei + E;
    const float fill = truncf(log2f((float)E / (float)N));

    u16* bufA; cudaGetSymbolAddress((void**)&bufA, g_bufA);
    u16* bufG; cudaGetSymbolAddress((void**)&bufG, g_bufG);
    u16* w1h;  cudaGetSymbolAddress((void**)&w1h, g_w1h);
    int* cntp; cudaGetSymbolAddress((void**)&cntp, g_cnt);

    cudaFuncSetAttribute(mmagemm_kernel,
                         cudaFuncAttributeMaxDynamicSharedMemorySize, 4 * SMB);

    const int T = 256;
    const int GB = (N + BM - 1) / BM;

    cudaStream_t s2;
    cudaStreamCreateWithFlags(&s2, cudaStreamNonBlocking);
    cudaEvent_t eFork, eJoin;
    cudaEventCreateWithFlags(&eFork, cudaEventDisableTiming);
    cudaEventCreateWithFlags(&eJoin, cudaEventDisableTiming);

    // fork: CSR build + Q prep on side stream, overlaps w1prep + GEMM1
    cudaEventRecord(eFork, 0);
    cudaStreamWaitEvent(s2, eFork, 0);

    cudaMemsetAsync(cntp, 0, N_NODES * sizeof(int), s2);           // node 0
    count_kernel<<<(E + T - 1) / T, T, 0, s2>>>(rows, E);          // 1
    offsets_q_kernel<<<OFF_BLOCKS + Q_BLOCKS, 1024, 0, s2>>>(N, fill, W2, W3); // 2
    fill_kernel<<<(E + T - 1) / T, T, 0, s2>>>(rows, cols, E);     // 3
    cudaEventRecord(eJoin, s2);

    w1prep_kernel<<<(HID * F_IN + T - 1) / T, T>>>(W1);            // 4
    mmagemm_kernel<<<GB, 256, 4 * SMB>>>(x, w1h, bufA, N, F_IN);   // 5 (profiled)

    // join, then agg1 (+Q epilogue) and the 16-wide second aggregation
    cudaStreamWaitEvent(0, eJoin, 0);
    agg1q_kernel<<<(N * 32 + T - 1) / T, T>>>(bufA, bufG, N, fill);
    {
        int warps = (N + 1) / 2;
        agg2_kernel<<<(warps * 32 + T - 1) / T, T>>>(bufG, b3, out, N, fill);
    }

    cudaEventDestroy(eFork);
    cudaEventDestroy(eJoin);
    cudaStreamDestroy(s2);
}

// round 17
// speedup vs baseline: 1.0743x; 1.0507x over previous
#include <cuda_runtime.h>
#include <cuda_fp16.h>
#include <cstdint>
#include <math.h>

#define N_NODES 100000
#define N_EDGES 3200000
#define F_IN    512
#define HID     128
#define N_CLS   16
#define CCOL_CAP (N_EDGES + 8 * N_NODES)

typedef unsigned short u16;

// ---------------- scratch (static device globals; no allocation) ----------
__device__ int   g_cnt[N_NODES];
__device__ int   g_off[N_NODES];          // 8-aligned row starts
__device__ float g_dinv[N_NODES];
__device__ int   g_total;
__device__ int   g_rank[N_EDGES];
__device__ int   g_ccol[CCOL_CAP];
__device__ u16   g_bufA[(size_t)N_NODES * HID];   // GEMM1 out; then dinv-scaled
__device__ u16   g_bufG[(size_t)N_NODES * N_CLS]; // gs = di*(relu(di*sum)@Q), fp16
__device__ u16   g_w1h[HID * F_IN];
__device__ float g_Q[HID * N_CLS];

// ---------------- helpers ---------------------------------------------------
__device__ __forceinline__ uint32_t smem_to_u32(const void* p) {
    uint32_t a;
    asm("{ .reg .u64 t; cvta.to.shared.u64 t, %1; cvt.u32.u64 %0, t; }"
        : "=r"(a) : "l"(p));
    return a;
}

#define LDSM4(r0, r1, r2, r3, addr)                                        \
    asm volatile("ldmatrix.sync.aligned.m8n8.x4.shared.b16 {%0,%1,%2,%3}, [%4];" \
                 : "=r"(r0), "=r"(r1), "=r"(r2), "=r"(r3) : "r"(addr))

#define MMA_F16(d, a, b)                                                   \
    asm volatile("mma.sync.aligned.m16n8k16.row.col.f32.f16.f16.f32 "      \
                 "{%0,%1,%2,%3}, {%4,%5,%6,%7}, {%8,%9}, {%0,%1,%2,%3};"   \
                 : "+f"((d)[0]), "+f"((d)[1]), "+f"((d)[2]), "+f"((d)[3])  \
                 : "r"((a)[0]), "r"((a)[1]), "r"((a)[2]), "r"((a)[3]),     \
                   "r"((b)[0]), "r"((b)[1]))

// ---------------- CSR construction ----------------------------------------
__global__ void count_kernel(const int* __restrict__ rows, int E) {
    int e = blockIdx.x * blockDim.x + threadIdx.x;
    if (e == 0) g_total = 0;
    if (e < E) g_rank[e] = atomicAdd(&g_cnt[rows[e]], 1);
}

// offsets (8-aligned rows) + dinv + Q (fused)
#define OFF_BLOCKS ((N_NODES + 1023) / 1024)
#define Q_BLOCKS   ((HID * N_CLS * 32 + 1023) / 1024)

__global__ void offsets_q_kernel(int n, float fill,
                                 const float* __restrict__ W2,
                                 const float* __restrict__ W3) {
    if (blockIdx.x >= OFF_BLOCKS) {
        int wg   = (blockIdx.x - OFF_BLOCKS) * 32 + (threadIdx.x >> 5);
        int lane = threadIdx.x & 31;
        if (wg < HID * N_CLS) {
            int k = wg / N_CLS, c = wg % N_CLS;
            float s = 0.f;
#pragma unroll
            for (int q = 0; q < 4; q++)
                s += W2[k * HID + lane + q * 32] * W3[c * HID + lane + q * 32];
            s += __shfl_xor_sync(0xffffffffu, s, 16);
            s += __shfl_xor_sync(0xffffffffu, s, 8);
            s += __shfl_xor_sync(0xffffffffu, s, 4);
            s += __shfl_xor_sync(0xffffffffu, s, 2);
            s += __shfl_xor_sync(0xffffffffu, s, 1);
            if (lane == 0) g_Q[k * N_CLS + c] = s;
        }
        return;
    }
    __shared__ int s[1024];
    __shared__ int base;
    int t = threadIdx.x;
    int i = blockIdx.x * 1024 + t;
    int v = (i < n) ? g_cnt[i] : 0;
    if (i < n) g_dinv[i] = rsqrtf((float)v + fill);
    int pv = (v + 7) & ~7;                 // pad row length to 8
    s[t] = pv;
    __syncthreads();
    for (int d = 1; d < 1024; d <<= 1) {
        int u = (t >= d) ? s[t - d] : 0;
        __syncthreads();
        s[t] += u;
        __syncthreads();
    }
    if (t == 1023) base = atomicAdd(&g_total, s[1023]);
    __syncthreads();
    if (i < n) g_off[i] = base + s[t] - pv;
}

__global__ void fill_kernel(const int* __restrict__ rows,
                            const int* __restrict__ cols, int E) {
    int e = blockIdx.x * blockDim.x + threadIdx.x;
    if (e < E)
        g_ccol[g_off[rows[e]] + g_rank[e]] = cols[e];
}

// ---------------- W1 prep ---------------------------------------------------
__global__ void w1prep_kernel(const float* __restrict__ W1) {
    int i = blockIdx.x * blockDim.x + threadIdx.x;
    if (i < HID * F_IN) {
        int n = i / F_IN, k = i % F_IN;
        __half h = __float2half_rn(W1[k * HID + n]);
        g_w1h[i] = *reinterpret_cast<u16*>(&h);
    }
}

// ---------------- HMMA fp16 GEMM (unchanged from R8 WIN) -------------------
#define BM   128
#define KCC  32
#define PADK 40
#define SMB  10240

__device__ __forceinline__ uint32_t qaddr(uint32_t base, int row0, int kb) {
    int L = threadIdx.x & 31;
    int r = row0 + (L & 15);
    int k = kb + (L >> 4) * 8;
    return base + (uint32_t)(r * (PADK * 2) + k * 2);
}

__global__ void __launch_bounds__(256, 2)
mmagemm_kernel(const float* __restrict__ Af,
               const u16* __restrict__ B,
               u16* __restrict__ C, int M, int K) {
    extern __shared__ __align__(16) char sm[];

    int tid  = threadIdx.x;
    int wid  = tid >> 5;
    int lane = tid & 31;
    int wr   = wid & 3;
    int wc   = wid >> 2;
    int m0   = blockIdx.x * BM;

    uint32_t sb = smem_to_u32(sm);
    float acc[2][8][4];
#pragma unroll
    for (int mt = 0; mt < 2; mt++)
#pragma unroll
        for (int nt = 0; nt < 8; nt++)
#pragma unroll
            for (int e = 0; e < 4; e++) acc[mt][nt][e] = 0.f;

    int arf = tid >> 3, aqf = tid & 7;
    int r16 = tid >> 2, q16 = tid & 3;

    float4 pa[4];
    uint4  pbv[2];

#pragma unroll
    for (int i = 0; i < 4; i++) {
        int r = arf + i * 32;
        pa[i] = make_float4(0.f, 0.f, 0.f, 0.f);
        if (m0 + r < M)
            pa[i] = *(const float4*)&Af[(size_t)(m0 + r) * K + aqf * 4];
    }
#pragma unroll
    for (int i = 0; i < 2; i++)
        pbv[i] = *(const uint4*)&B[(size_t)(r16 + i * 64) * K + q16 * 8];
    {
        u16* BsP = (u16*)(sm);
        u16* AsP = (u16*)(sm + 2 * SMB);
#pragma unroll
        for (int i = 0; i < 2; i++)
            *(uint4*)&BsP[(r16 + i * 64) * PADK + q16 * 8] = pbv[i];
#pragma unroll
        for (int i = 0; i < 4; i++) {
            __half2 h0 = __floats2half2_rn(pa[i].x, pa[i].y);
            __half2 h1 = __floats2half2_rn(pa[i].z, pa[i].w);
            *(uint2*)&AsP[(arf + i * 32) * PADK + aqf * 4] =
                make_uint2(*(unsigned*)&h0, *(unsigned*)&h1);
        }
    }
    __syncthreads();

    int nc = K / KCC;
    for (int c = 0; c < nc; c++) {
        int s = c & 1;
        if (c + 1 < nc) {
            int k0 = (c + 1) * KCC;
#pragma unroll
            for (int i = 0; i < 4; i++) {
                int r = arf + i * 32;
                pa[i] = make_float4(0.f, 0.f, 0.f, 0.f);
                if (m0 + r < M)
                    pa[i] = *(const float4*)&Af[(size_t)(m0 + r) * K + k0 + aqf * 4];
            }
#pragma unroll
            for (int i = 0; i < 2; i++)
                pbv[i] = *(const uint4*)&B[(size_t)(r16 + i * 64) * K + k0 + q16 * 8];
        }

        uint32_t bs_base = sb + s * SMB;
        uint32_t as_base = sb + 2 * SMB + s * SMB;
#pragma unroll
        for (int ks = 0; ks < KCC; ks += 16) {
            uint32_t bf[8][2];
#pragma unroll
            for (int g = 0; g < 4; g++) {
                uint32_t r0, r1, r2, r3;
                LDSM4(r0, r1, r2, r3, qaddr(bs_base, wc * 64 + g * 16, ks));
                bf[g * 2][0] = r0; bf[g * 2][1] = r2;
                bf[g * 2 + 1][0] = r1; bf[g * 2 + 1][1] = r3;
            }
            uint32_t ah[2][4];
#pragma unroll
            for (int mt = 0; mt < 2; mt++)
                LDSM4(ah[mt][0], ah[mt][1], ah[mt][2], ah[mt][3],
                      qaddr(as_base, wr * 32 + mt * 16, ks));
#pragma unroll
            for (int mt = 0; mt < 2; mt++)
#pragma unroll
                for (int nt = 0; nt < 8; nt++)
                    MMA_F16(acc[mt][nt], ah[mt], bf[nt]);
        }

        if (c + 1 < nc) {
            int s2 = 1 - s;
            u16* BsP = (u16*)(sm + s2 * SMB);
            u16* AsP = (u16*)(sm + 2 * SMB + s2 * SMB);
#pragma unroll
            for (int i = 0; i < 2; i++)
                *(uint4*)&BsP[(r16 + i * 64) * PADK + q16 * 8] = pbv[i];
#pragma unroll
            for (int i = 0; i < 4; i++) {
                __half2 h0 = __floats2half2_rn(pa[i].x, pa[i].y);
                __half2 h1 = __floats2half2_rn(pa[i].z, pa[i].w);
                *(uint2*)&AsP[(arf + i * 32) * PADK + aqf * 4] =
                    make_uint2(*(unsigned*)&h0, *(unsigned*)&h1);
            }
        }
        __syncthreads();
    }

    int rbase = m0 + wr * 32 + (lane >> 2);
    int cbase = wc * 64 + (lane & 3) * 2;
#pragma unroll
    for (int mt = 0; mt < 2; mt++)
#pragma unroll
        for (int nt = 0; nt < 8; nt++) {
            int r = rbase + mt * 16;
            int cc = cbase + nt * 8;
            if (r < M) {
                __half2 v = __floats2half2_rn(acc[mt][nt][0], acc[mt][nt][1]);
                *(unsigned*)&C[(size_t)r * 128 + cc] = *reinterpret_cast<unsigned*>(&v);
            }
            if (r + 8 < M) {
                __half2 v = __floats2half2_rn(acc[mt][nt][2], acc[mt][nt][3]);
                *(unsigned*)&C[(size_t)(r + 8) * 128 + cc] = *reinterpret_cast<unsigned*>(&v);
            }
        }
}

// ---------------- scale: bufA *= dinv[row] (in place, fp16) ----------------
__global__ void scale_kernel(u16* __restrict__ h, int n) {
    int idx = blockIdx.x * blockDim.x + threadIdx.x;   // one uint4 = 8 halves
    int row = idx >> 4;
    if (row >= n) return;
    float di = g_dinv[row];
    uint4 v = ((const uint4*)h)[idx];
    __half2* p = reinterpret_cast<__half2*>(&v);
#pragma unroll
    for (int i = 0; i < 4; i++) {
        float2 f = __half22float2(p[i]);
        p[i] = __floats2half2_rn(f.x * di, f.y * di);
    }
    ((uint4*)h)[idx] = v;
}

// ---------------- agg1 + Q: weight-free gather ------------------------------
// sum[k] = Sum_e hs[col][k] + fill*hs[row][k];  a = relu(di*sum);
// gs[row] = di * (a @ Q)  stored fp16
__device__ __forceinline__ void gadd(float4& acc, uint2 raw) {
    float2 f0 = __half22float2(*reinterpret_cast<__half2*>(&raw.x));
    float2 f1 = __half22float2(*reinterpret_cast<__half2*>(&raw.y));
    acc.x += f0.x; acc.y += f0.y;
    acc.z += f1.x; acc.w += f1.y;
}

__global__ void agg1q_kernel(const u16* __restrict__ h,
                             u16* __restrict__ g, int n, float fill) {
    __shared__ float sQ[N_CLS * HID];
    for (int i = threadIdx.x; i < N_CLS * HID; i += blockDim.x) {
        int c = i / HID, k = i % HID;
        sQ[i] = g_Q[k * N_CLS + c];
    }
    __syncthreads();

    int warp = (blockIdx.x * blockDim.x + threadIdx.x) >> 5;
    int lane = threadIdx.x & 31;
    if (warp >= n) return;
    const uint2* hv = (const uint2*)h;

    float di = g_dinv[warp];
    // self term: fill * hs[row]
    float4 acc;
    {
        uint2 r = hv[(size_t)warp * 32 + lane];
        float2 f0 = __half22float2(*reinterpret_cast<__half2*>(&r.x));
        float2 f1 = __half22float2(*reinterpret_cast<__half2*>(&r.y));
        acc = make_float4(fill * f0.x, fill * f0.y, fill * f1.x, fill * f1.y);
    }

    int s = g_off[warp];
    int c = g_cnt[warp];
    int j = 0;
    for (; j + 8 <= c; j += 8) {
        int4 c0 = *(const int4*)&g_ccol[s + j];       // 8-aligned start
        int4 c1 = *(const int4*)&g_ccol[s + j + 4];
        uint2 u0 = hv[(size_t)c0.x * 32 + lane];
        uint2 u1 = hv[(size_t)c0.y * 32 + lane];
        uint2 u2 = hv[(size_t)c0.z * 32 + lane];
        uint2 u3 = hv[(size_t)c0.w * 32 + lane];
        uint2 u4 = hv[(size_t)c1.x * 32 + lane];
        uint2 u5 = hv[(size_t)c1.y * 32 + lane];
        uint2 u6 = hv[(size_t)c1.z * 32 + lane];
        uint2 u7 = hv[(size_t)c1.w * 32 + lane];
        gadd(acc, u0); gadd(acc, u1); gadd(acc, u2); gadd(acc, u3);
        gadd(acc, u4); gadd(acc, u5); gadd(acc, u6); gadd(acc, u7);
    }
    for (; j < c; j++) {
        int col = __ldg(&g_ccol[s + j]);
        gadd(acc, hv[(size_t)col * 32 + lane]);
    }
    // a = relu(di * sum)
    acc.x = fmaxf(di * acc.x, 0.f);
    acc.y = fmaxf(di * acc.y, 0.f);
    acc.z = fmaxf(di * acc.z, 0.f);
    acc.w = fmaxf(di * acc.w, 0.f);

#pragma unroll
    for (int cc = 0; cc < N_CLS; cc++) {
        float4 q = *(const float4*)&sQ[cc * 128 + lane * 4];
        float  p = acc.x * q.x + acc.y * q.y + acc.z * q.z + acc.w * q.w;
        p += __shfl_xor_sync(0xffffffffu, p, 16);
        p += __shfl_xor_sync(0xffffffffu, p, 8);
        p += __shfl_xor_sync(0xffffffffu, p, 4);
        p += __shfl_xor_sync(0xffffffffu, p, 2);
        p += __shfl_xor_sync(0xffffffffu, p, 1);
        if (lane == 0) {
            __half hv16 = __float2half_rn(di * p);   // gs = di * (a@Q)
            g[(size_t)warp * N_CLS + cc] = *reinterpret_cast<u16*>(&hv16);
        }
    }
}

// ---------------- agg2: out = di*(Sum gs[col] + fill*gs[row]) + b3 ---------
__global__ void agg2_kernel(const u16* __restrict__ g,
                            const float* __restrict__ b3,
                            float* __restrict__ out, int n, float fill) {
    __shared__ float sb[N_CLS];
    if (threadIdx.x < N_CLS) sb[threadIdx.x] = b3[threadIdx.x];
    __syncthreads();

    int wp   = (blockIdx.x * blockDim.x + threadIdx.x) >> 5;
    int lane = threadIdx.x & 31;
    int half = lane >> 4, lp = lane & 15;
    int row  = wp * 2 + half;
    if (wp * 2 >= n) return;
    bool active = row < n;
    int rsafe = active ? row : 0;

    float di = active ? g_dinv[rsafe] : 0.f;
    float acc = fill * __half2float(
        *reinterpret_cast<const __half*>(&g[(size_t)rsafe * N_CLS + lp]));

    int s = g_off[rsafe];
    int c = active ? g_cnt[rsafe] : 0;
    int cO = __shfl_xor_sync(0xffffffffu, c, 16);
    int cm = max(c, cO);
    for (int j = 0; j < cm; j += 8) {
        int cols[8];
        float m[8];
#pragma unroll
        for (int q = 0; q < 8; q++) {
            bool act = (j + q) < c;
            cols[q] = act ? __ldg(&g_ccol[s + j + q]) : rsafe;
            m[q]    = act ? 1.f : 0.f;
        }
#pragma unroll
        for (int q = 0; q < 8; q++) {
            float gv = __half2float(*reinterpret_cast<const __half*>(
                &g[(size_t)cols[q] * N_CLS + lp]));
            acc += m[q] * gv;
        }
    }
    if (active) out[(size_t)row * N_CLS + lp] = di * acc + sb[lp];
}

// ---------------- launch ---------------------------------------------------
extern "C" void kernel_launch(void* const* d_in, const int* in_sizes, int n_in,
                              void* d_out, int out_size) {
    const float* x  = (const float*)d_in[0];
    const int*   ei = (const int*)d_in[1];
    const float* W1 = (const float*)d_in[2];
    const float* W2 = (const float*)d_in[3];
    const float* W3 = (const float*)d_in[4];
    const float* b3 = (const float*)d_in[5];
    float* out = (float*)d_out;

    const int E = in_sizes[1] / 2;
    const int N = in_sizes[0] / F_IN;
    const int* rows = ei;
    const int* cols = ei + E;
    const float fill = truncf(log2f((float)E / (float)N));

    u16* bufA; cudaGetSymbolAddress((void**)&bufA, g_bufA);
    u16* bufG; cudaGetSymbolAddress((void**)&bufG, g_bufG);
    u16* w1h;  cudaGetSymbolAddress((void**)&w1h, g_w1h);
    int* cntp; cudaGetSymbolAddress((void**)&cntp, g_cnt);

    cudaFuncSetAttribute(mmagemm_kernel,
                         cudaFuncAttributeMaxDynamicSharedMemorySize, 4 * SMB);

    const int T = 256;
    const int GB = (N + BM - 1) / BM;

    cudaStream_t s2;
    cudaStreamCreateWithFlags(&s2, cudaStreamNonBlocking);
    cudaEvent_t eFork, eJoin;
    cudaEventCreateWithFlags(&eFork, cudaEventDisableTiming);
    cudaEventCreateWithFlags(&eJoin, cudaEventDisableTiming);

    // fork: CSR build + Q prep on side stream, overlaps w1prep + GEMM1
    cudaEventRecord(eFork, 0);
    cudaStreamWaitEvent(s2, eFork, 0);

    cudaMemsetAsync(cntp, 0, N_NODES * sizeof(int), s2);
    count_kernel<<<(E + T - 1) / T, T, 0, s2>>>(rows, E);
    offsets_q_kernel<<<OFF_BLOCKS + Q_BLOCKS, 1024, 0, s2>>>(N, fill, W2, W3);
    fill_kernel<<<(E + T - 1) / T, T, 0, s2>>>(rows, cols, E);
    cudaEventRecord(eJoin, s2);

    w1prep_kernel<<<(HID * F_IN + T - 1) / T, T>>>(W1);
    mmagemm_kernel<<<GB, 256, 4 * SMB>>>(x, w1h, bufA, N, F_IN);

    // join, then scale + weight-free aggregations
    cudaStreamWaitEvent(0, eJoin, 0);
    scale_kernel<<<(N * 16 + T - 1) / T, T>>>(bufA, N);
    agg1q_kernel<<<(N * 32 + T - 1) / T, T>>>(bufA, bufG, N, fill);
    {
        int warps = (N + 1) / 2;
        agg2_kernel<<<(warps * 32 + T - 1) / T, T>>>(bufG, b3, out, N, fill);
    }

    cudaEventDestroy(eFork);
    cudaEventDestroy(eJoin);
    cudaStreamDestroy(s2);
}